// round 17
// baseline (speedup 1.0000x reference)
#include <cuda_runtime.h>

// ---------------------------------------------------------------------------
// PureGNN rank collapse, u-scaled, flag-fused launches:
//   K1 = [prep | edge1], K2 = [node1 | edge2], K3 = [node2 | edge3],
//   then node3+pool, then readout.  6 launches total (was 9).
// Node role = first NPB blocks (wave-1 guaranteed), produces u/acc and raises a
// flag; edge role spins on the flag (no gridDepSync needed: ALL its inputs are
// produced by this kernel's node role or are pure inputs).
// Basis: [P^3 x, P^3 1, P^2 1, P 1, 1] -> pooled S -> tiny readout.
// Invariants restored in-pipeline: g_deg by K1, g_fC by K2, g_fA by K3,
// g_fB by pool, g_S by readout. Loader zero-init seeds the first epoch.
// RULES: device globals only in device code (ATS). PDL pre-sync reads only
//        pure inputs / K-2-or-older. COO+RED is sector-minimal (R15).
// ---------------------------------------------------------------------------

#define NN 50000
#define NE 1600000
#define NG 32
#define ED 128
#define NPB 196          // node-role blocks: 196*256 = 50176 >= NN
#define EEB 6250         // edge-role blocks: 6250*256 = NE exactly

__device__ float  g_deg [NN];     // invariant: 0 at entry (restored by K1)
__device__ float  g_dinv[NN];
__device__ float2 g_u   [NN];
__device__ float2 g_acc [NN];
__device__ float  g_k1y [NN];
__device__ float  g_k2y [NN];
__device__ float  g_S   [NG * 5]; // invariant: 0 (restored by readout)
__device__ unsigned g_fC, g_fA, g_fB;  // phase flags, 0-invariant

// ---------------------------------------------------------------------------
// degree count: 2 edges/thread; keeps gridDepSync so prior replay's pool and
// readout are transitively complete before K1's node role writes state.
__global__ void k_count(const int* __restrict__ dst) {
    int e = (blockIdx.x * blockDim.x + threadIdx.x) * 2;
    int2 d2;
    bool full = (e + 1 < NE);
    if (full) d2 = *(const int2*)(dst + e);         // pure input
    cudaGridDependencySynchronize();
    if (full) {
        atomicAdd(&g_deg[d2.x], 1.0f);
        atomicAdd(&g_deg[d2.y], 1.0f);
    } else if (e < NE) {
        atomicAdd(&g_deg[dst[e]], 1.0f);
    }
    cudaTriggerProgrammaticLaunchCompletion();
}

// ---------------------------------------------------------------------------
// Fused phase kernel. K=1: prep|edge1 (flag fC). K=2: node1|edge2 (fA, resets
// fC). K=3: node2|edge3 (fB, resets fA).
template <int K>
__global__ __launch_bounds__(256)
void k_fused(const float* __restrict__ x,
             const int* __restrict__ src, const int* __restrict__ dst) {
    int b = blockIdx.x;
    if (b < NPB) {
        // ---- node role ----
        int i = b * 256 + threadIdx.x;
        float xi = 0.0f;
        if (K == 1 && i < NN) xi = x[i];            // pure input: pre-sync
        cudaGridDependencySynchronize();            // prev kernel fully done
        if (i < NN) {
            if (K == 1) {
                float di = rsqrtf(g_deg[i] + 1.0f); // +1 self-loop
                g_deg[i] = 0.0f;                    // restore invariant
                g_dinv[i] = di;
                g_u[i]   = make_float2(di * xi, di);
                g_acc[i] = make_float2(0.0f, 0.0f);
            } else {
                float di = g_dinv[i];
                float2 a = g_acc[i];
                float2 u = g_u[i];
                float zx = di * (a.x + u.x);
                float zy = di * (a.y + u.y);
                if (K == 2) g_k1y[i] = zy; else g_k2y[i] = zy;
                g_u[i]   = make_float2(di * zx, di * zy);
                g_acc[i] = make_float2(0.0f, 0.0f);
            }
        }
        if (threadIdx.x == 0 && b == 0) {           // reset upstream flag
            if (K == 2) g_fC = 0u;
            if (K == 3) g_fA = 0u;
        }
        __threadfence();                            // release this thread's writes
        __syncthreads();                            // all threads' fences done
        if (threadIdx.x == 0) {
            unsigned* f = (K == 1) ? &g_fC : (K == 2) ? &g_fA : &g_fB;
            atomicAdd(f, 1u);
        }
        cudaTriggerProgrammaticLaunchCompletion();
    } else {
        // ---- edge role: inputs = pure (src/dst) + this kernel's node output ----
        int e = (b - NPB) * 256 + threadIdx.x;      // exact, no tail
        int s = src[e];
        int d = dst[e];
        volatile unsigned* f = (K == 1) ? &g_fC : (K == 2) ? &g_fA : &g_fB;
        while (*f < NPB) __nanosleep(64);
        __threadfence();                            // acquire + compiler fence
        float2 v = g_u[s];
        atomicAdd(&g_acc[d], v);
        cudaTriggerProgrammaticLaunchCompletion();
    }
}

// ---------------------------------------------------------------------------
// node3 + per-graph pooling (batch sorted -> warp-uniform fast path).
// Resets g_fB (post-sync: K3 fully complete).
__global__ void k_node3_pool(const int* __restrict__ batch) {
    __shared__ float sh[NG * 5];
    int i = blockIdx.x * blockDim.x + threadIdx.x;
    int lane = threadIdx.x & 31;
    bool act = (i < NN);
    int g = 0;
    float k1 = 0.0f;
    if (act) { g = batch[i]; k1 = g_k1y[i]; }      // pure + K-2: pre-sync
    for (int t = threadIdx.x; t < NG * 5; t += blockDim.x) sh[t] = 0.0f;
    __syncthreads();

    cudaGridDependencySynchronize();                // K3 complete
    if (i == 0) g_fB = 0u;                          // restore invariant

    float z3x = 0.0f, z3y = 0.0f, k2 = 0.0f;
    if (act) {
        float di = g_dinv[i];
        float2 a = g_acc[i];
        float2 u = g_u[i];
        z3x = di * (a.x + u.x);
        z3y = di * (a.y + u.y);
        k2  = g_k2y[i];
    }
    unsigned m = __ballot_sync(0xffffffffu, act);
    int g0 = __shfl_sync(0xffffffffu, g, 0);
    bool uni = (m == 0xffffffffu) && __all_sync(0xffffffffu, g == g0);
    if (uni) {
        #pragma unroll
        for (int o = 16; o > 0; o >>= 1) {
            z3x += __shfl_down_sync(0xffffffffu, z3x, o);
            z3y += __shfl_down_sync(0xffffffffu, z3y, o);
            k2  += __shfl_down_sync(0xffffffffu, k2,  o);
            k1  += __shfl_down_sync(0xffffffffu, k1,  o);
        }
        if (lane == 0) {
            atomicAdd(&sh[g0 * 5 + 0], z3x);
            atomicAdd(&sh[g0 * 5 + 1], z3y);
            atomicAdd(&sh[g0 * 5 + 2], k2);
            atomicAdd(&sh[g0 * 5 + 3], k1);
            atomicAdd(&sh[g0 * 5 + 4], 32.0f);
        }
    } else if (act) {
        atomicAdd(&sh[g * 5 + 0], z3x);
        atomicAdd(&sh[g * 5 + 1], z3y);
        atomicAdd(&sh[g * 5 + 2], k2);
        atomicAdd(&sh[g * 5 + 3], k1);
        atomicAdd(&sh[g * 5 + 4], 1.0f);
    }
    __syncthreads();
    for (int t = threadIdx.x; t < NG * 5; t += blockDim.x)
        if (sh[t] != 0.0f) atomicAdd(&g_S[t], sh[t]);
    cudaTriggerProgrammaticLaunchCompletion();
}

// ---------------------------------------------------------------------------
// Readout (PDL): weight chain pre-sync; g_S read post-sync and zeroed.
__global__ void k_readout(const float* __restrict__ lin_w, const float* __restrict__ lin_b,
                          const float* __restrict__ gcn_w, const float* __restrict__ gcn_b,
                          const float* __restrict__ r1_w,  const float* __restrict__ r1_b,
                          const float* __restrict__ r2_w,  const float* __restrict__ r2_b,
                          float* __restrict__ out) {
    __shared__ float vin[5][ED];
    __shared__ float vout[5][ED];
    __shared__ float pooled[NG][ED];
    __shared__ float hr[NG][ED];
    __shared__ float sS[NG * 5];

    int tid = threadIdx.x;
    int j   = tid & 127;
    int grp = tid >> 7;      // 0..3

    if (grp == 0) { vin[0][j] = lin_w[j]; vin[1][j] = lin_b[j]; }  // pure inputs
    __syncthreads();

    int nrows = 2;
    for (int l = 0; l < 3; l++) {
        const float* W = gcn_w + l * ED * ED;
        if (grp < nrows) {
            float a0 = 0.0f, a1 = 0.0f;
            #pragma unroll 4
            for (int i = 0; i < ED; i += 2) {
                a0 = fmaf(vin[grp][i],     W[i * ED + j],       a0);
                a1 = fmaf(vin[grp][i + 1], W[(i + 1) * ED + j], a1);
            }
            vout[grp][j] = a0 + a1;
        }
        if (grp == 0) vout[nrows][j] = gcn_b[l * ED + j];
        nrows++;
        __syncthreads();
        for (int r = grp; r < nrows; r += 4) vin[r][j] = vout[r][j];
        __syncthreads();
    }

    cudaGridDependencySynchronize();          // g_S ready
    for (int t = tid; t < NG * 5; t += 512) { sS[t] = g_S[t]; g_S[t] = 0.0f; }
    __syncthreads();

    for (int g = grp * 8; g < grp * 8 + 8; g++) {
        float p = 0.0f;
        #pragma unroll
        for (int r = 0; r < 5; r++) p = fmaf(sS[g * 5 + r], vin[r][j], p);
        pooled[g][j] = p;
    }
    __syncthreads();

    float bj = r1_b[j];
    for (int g = grp * 8; g < grp * 8 + 8; g++) {
        float a0 = bj, a1 = 0.0f, a2 = 0.0f, a3 = 0.0f;
        #pragma unroll 2
        for (int i = 0; i < ED; i += 4) {
            a0 = fmaf(pooled[g][i],     r1_w[i * ED + j],       a0);
            a1 = fmaf(pooled[g][i + 1], r1_w[(i + 1) * ED + j], a1);
            a2 = fmaf(pooled[g][i + 2], r1_w[(i + 2) * ED + j], a2);
            a3 = fmaf(pooled[g][i + 3], r1_w[(i + 3) * ED + j], a3);
        }
        hr[g][j] = tanhf((a0 + a1) + (a2 + a3));
    }
    __syncthreads();

    int warp = tid >> 5;
    int lane = tid & 31;
    for (int g = warp; g < NG; g += 16) {
        float s = hr[g][lane]      * r2_w[lane]
                + hr[g][lane + 32] * r2_w[lane + 32]
                + hr[g][lane + 64] * r2_w[lane + 64]
                + hr[g][lane + 96] * r2_w[lane + 96];
        #pragma unroll
        for (int o = 16; o > 0; o >>= 1) s += __shfl_down_sync(0xffffffffu, s, o);
        if (lane == 0) out[g] = s + r2_b[0];
    }
}

// ---------------------------------------------------------------------------
template <typename KernT, typename... Args>
static inline void launch_pdl(KernT kern, int grid, int block, Args... args) {
    cudaLaunchConfig_t cfg = {};
    cfg.gridDim = dim3(grid, 1, 1);
    cfg.blockDim = dim3(block, 1, 1);
    cfg.dynamicSmemBytes = 0;
    cfg.stream = 0;
    cudaLaunchAttribute attr[1];
    attr[0].id = cudaLaunchAttributeProgrammaticStreamSerialization;
    attr[0].val.programmaticStreamSerializationAllowed = 1;
    cfg.attrs = attr;
    cfg.numAttrs = 1;
    cudaLaunchKernelEx(&cfg, kern, args...);
}

extern "C" void kernel_launch(void* const* d_in, const int* in_sizes, int n_in,
                              void* d_out, int out_size) {
    const float* x     = (const float*)d_in[0];
    const int*   eidx  = (const int*)  d_in[1];
    const int*   batch = (const int*)  d_in[2];
    const float* lin_w = (const float*)d_in[3];
    const float* lin_b = (const float*)d_in[4];
    const float* gcn_w = (const float*)d_in[5];
    const float* gcn_b = (const float*)d_in[6];
    const float* r1_w  = (const float*)d_in[7];
    const float* r1_b  = (const float*)d_in[8];
    const float* r2_w  = (const float*)d_in[9];
    const float* r2_b  = (const float*)d_in[10];
    float* out = (float*)d_out;

    const int* src = eidx;          // edge_index[0]
    const int* dst = eidx + NE;     // edge_index[1]

    int nb = (NN + 255) / 256;                 // 196
    int cb = (NE + 2 * 256 - 1) / (2 * 256);   // 3125
    int fb = NPB + EEB;                        // 6446

    launch_pdl(k_count, cb, 256, dst);
    launch_pdl(k_fused<1>, fb, 256, x, src, dst);   // prep  | edge1
    launch_pdl(k_fused<2>, fb, 256, x, src, dst);   // node1 | edge2
    launch_pdl(k_fused<3>, fb, 256, x, src, dst);   // node2 | edge3
    launch_pdl(k_node3_pool, nb, 256, batch);       // z3 + pool -> g_S
    launch_pdl(k_readout, 1, 512,
               lin_w, lin_b, gcn_w, gcn_b, r1_w, r1_b, r2_w, r2_b, out);
}